// round 9
// baseline (speedup 1.0000x reference)
#include <cuda_runtime.h>
#include <cstdint>

#define NN 100000
#define NE 1600000
#define DH 64
#define AS_STRIDE 68
#define WS_STRIDE 132

// ---------------- scratch (no allocations allowed) ----------------
__device__ float g_agg[(size_t)NN * DH];
__device__ float g_h1 [(size_t)NN * DH];
__device__ float g_Wn1[64 * WS_STRIDE];   // [n][k] tf32-rounded, k = rel(0:64)|root(64:128)
__device__ float g_Wn2[64 * WS_STRIDE];
__device__ int   g_esrc[NE];
__device__ int   g_cnt[NN];
__device__ int   g_offs[NN + 1];
__device__ int   g_cursor[NN];
__device__ int   g_is64;

__device__ __forceinline__ float to_tf32(float x) {
    unsigned u;
    asm("cvt.rna.tf32.f32 %0, %1;" : "=r"(u) : "f"(x));
    return __uint_as_float(u);
}

__device__ __forceinline__ void mma_tf32(float c[4], const unsigned a[4], const unsigned b[2]) {
    asm("mma.sync.aligned.m16n8k8.row.col.f32.tf32.tf32.f32 "
        "{%0,%1,%2,%3}, {%4,%5,%6,%7}, {%8,%9}, {%0,%1,%2,%3};"
        : "+f"(c[0]), "+f"(c[1]), "+f"(c[2]), "+f"(c[3])
        : "r"(a[0]), "r"(a[1]), "r"(a[2]), "r"(a[3]), "r"(b[0]), "r"(b[1]));
}

// ---------------- zero cnt + detect edge_index dtype ----------------
__global__ void zero_detect(const void* __restrict__ ei, int* __restrict__ cnt) {
    int i = blockIdx.x * blockDim.x + threadIdx.x;
    if (i < NN) cnt[i] = 0;
    if (i == 0) {
        const long long* p = (const long long*)ei;
        bool all64 = true;
        #pragma unroll
        for (int j = 0; j < 8; ++j) {
            long long v = p[j];
            if (v < 0 || v >= NN) all64 = false;
        }
        g_is64 = all64 ? 1 : 0;
    }
}

// ---------------- histogram over dst (4 edges/thread) ----------------
__global__ void hist_dst(const void* __restrict__ ei, int* __restrict__ cnt) {
    int i = (blockIdx.x * blockDim.x + threadIdx.x) * 4;
    if (i >= NE) return;
    int d0, d1, d2, d3;
    if (g_is64) {
        longlong4 q = *reinterpret_cast<const longlong4*>((const long long*)ei + NE + i);
        d0 = (int)q.x; d1 = (int)q.y; d2 = (int)q.z; d3 = (int)q.w;
    } else {
        int4 q = *reinterpret_cast<const int4*>((const int*)ei + NE + i);
        d0 = q.x; d1 = q.y; d2 = q.z; d3 = q.w;
    }
    atomicAdd(&cnt[d0], 1);
    atomicAdd(&cnt[d1], 1);
    atomicAdd(&cnt[d2], 1);
    atomicAdd(&cnt[d3], 1);
}

// ---------------- single-block exclusive scan -> offs + cursor ----------------
// 1024 threads, thread t owns counts [t*100, t*100+100).
__global__ void scan_all(const int* __restrict__ cnt,
                         int* __restrict__ offs, int* __restrict__ cursor) {
    __shared__ int sh[1024];
    const int t = threadIdx.x;
    const int C = 100;
    int base = t * C;
    int s = 0;
    if (base < NN) {
        const int4* p4 = reinterpret_cast<const int4*>(cnt + base);
        #pragma unroll 5
        for (int i = 0; i < C / 4; ++i) {
            int4 v = p4[i];
            s += v.x + v.y + v.z + v.w;
        }
    }
    sh[t] = s;
    __syncthreads();
    #pragma unroll
    for (int off = 1; off < 1024; off <<= 1) {
        int v = (t >= off) ? sh[t - off] : 0;
        __syncthreads();
        sh[t] += v;
        __syncthreads();
    }
    if (base < NN) {
        int run = sh[t] - s;
        #pragma unroll 10
        for (int i = 0; i < C; ++i) {
            offs[base + i]   = run;
            cursor[base + i] = run;
            run += cnt[base + i];
        }
    }
    if (t == 0) offs[NN] = NE;
}

// ---------------- place edges (CSR fill) ----------------
__global__ void place_edges(const void* __restrict__ ei,
                            int* __restrict__ cursor, int* __restrict__ esrc) {
    int i = (blockIdx.x * blockDim.x + threadIdx.x) * 4;
    if (i >= NE) return;
    int s0, s1, s2, s3, d0, d1, d2, d3;
    if (g_is64) {
        const long long* p = (const long long*)ei;
        longlong4 qs = *reinterpret_cast<const longlong4*>(p + i);
        longlong4 qd = *reinterpret_cast<const longlong4*>(p + NE + i);
        s0 = (int)qs.x; s1 = (int)qs.y; s2 = (int)qs.z; s3 = (int)qs.w;
        d0 = (int)qd.x; d1 = (int)qd.y; d2 = (int)qd.z; d3 = (int)qd.w;
    } else {
        const int* p = (const int*)ei;
        int4 qs = *reinterpret_cast<const int4*>(p + i);
        int4 qd = *reinterpret_cast<const int4*>(p + NE + i);
        s0 = qs.x; s1 = qs.y; s2 = qs.z; s3 = qs.w;
        d0 = qd.x; d1 = qd.y; d2 = qd.z; d3 = qd.w;
    }
    esrc[atomicAdd(&cursor[d0], 1)] = s0;
    esrc[atomicAdd(&cursor[d1], 1)] = s1;
    esrc[atomicAdd(&cursor[d2], 1)] = s2;
    esrc[atomicAdd(&cursor[d3], 1)] = s3;
}

// ---------------- both weight tensors -> tf32 [n][k] ----------------
__global__ void prep_w2(const float* __restrict__ W1rel, const float* __restrict__ W1rt,
                        const float* __restrict__ W2rel, const float* __restrict__ W2rt,
                        float* __restrict__ Wn1, float* __restrict__ Wn2) {
    int i = blockIdx.x * blockDim.x + threadIdx.x;
    int layer = (i >= 64 * WS_STRIDE);
    int j = i - layer * 64 * WS_STRIDE;
    if (j < 64 * WS_STRIDE && i < 2 * 64 * WS_STRIDE) {
        int n = j / WS_STRIDE;
        int k = j - n * WS_STRIDE;
        const float* Wrel = layer ? W2rel : W1rel;
        const float* Wrt  = layer ? W2rt  : W1rt;
        float v = 0.f;
        if (k < 64)       v = Wrel[n * 64 + k];
        else if (k < 128) v = Wrt [n * 64 + (k - 64)];
        (layer ? Wn2 : Wn1)[j] = to_tf32(v);
    }
}

// ---------------- gather: 1 warp/node, float2/lane, 8-edge unroll ----------------
__global__ void __launch_bounds__(256)
gather_agg(const float* __restrict__ feat,
           const int* __restrict__ offs,
           const int* __restrict__ esrc,
           float* __restrict__ agg) {
    int node = blockIdx.x * (blockDim.x >> 5) + (threadIdx.x >> 5);
    if (node >= NN) return;
    int lane = threadIdx.x & 31;
    int s0 = offs[node];
    int s1 = offs[node + 1];
    const float2* f2 = reinterpret_cast<const float2*>(feat);
    float sx = 0.f, sy = 0.f;
    int j = s0;
    for (; j + 8 <= s1; j += 8) {           // 8 independent LDG.64 in flight
        int e0 = esrc[j],     e1 = esrc[j + 1], e2 = esrc[j + 2], e3 = esrc[j + 3];
        int e4 = esrc[j + 4], e5 = esrc[j + 5], e6 = esrc[j + 6], e7 = esrc[j + 7];
        float2 v0 = f2[(size_t)e0 * 32 + lane];
        float2 v1 = f2[(size_t)e1 * 32 + lane];
        float2 v2 = f2[(size_t)e2 * 32 + lane];
        float2 v3 = f2[(size_t)e3 * 32 + lane];
        float2 v4 = f2[(size_t)e4 * 32 + lane];
        float2 v5 = f2[(size_t)e5 * 32 + lane];
        float2 v6 = f2[(size_t)e6 * 32 + lane];
        float2 v7 = f2[(size_t)e7 * 32 + lane];
        sx += (v0.x + v1.x) + (v2.x + v3.x) + (v4.x + v5.x) + (v6.x + v7.x);
        sy += (v0.y + v1.y) + (v2.y + v3.y) + (v4.y + v5.y) + (v6.y + v7.y);
    }
    for (; j + 4 <= s1; j += 4) {
        int e0 = esrc[j], e1 = esrc[j + 1], e2 = esrc[j + 2], e3 = esrc[j + 3];
        float2 v0 = f2[(size_t)e0 * 32 + lane];
        float2 v1 = f2[(size_t)e1 * 32 + lane];
        float2 v2 = f2[(size_t)e2 * 32 + lane];
        float2 v3 = f2[(size_t)e3 * 32 + lane];
        sx += (v0.x + v1.x) + (v2.x + v3.x);
        sy += (v0.y + v1.y) + (v2.y + v3.y);
    }
    for (; j < s1; ++j) {
        float2 v = f2[(size_t)esrc[j] * 32 + lane];
        sx += v.x; sy += v.y;
    }
    reinterpret_cast<float2*>(agg)[(size_t)node * 32 + lane] = make_float2(sx, sy);
}

// ---------------- tf32 tensor-core dual-GEMM (+ fused head on FINAL) ----------
template<bool FINAL>
__global__ void __launch_bounds__(256)
gemm_tc(const float* __restrict__ A0,    // agg [NN,64]
        const float* __restrict__ A1,    // xin [NN,64]
        const float* __restrict__ Wn,    // [64][WS_STRIDE] tf32
        const float* __restrict__ bias,  // [64]
        const float* __restrict__ Wlin,  // [3,64]  (FINAL)
        const float* __restrict__ blin,  // [3]     (FINAL)
        float* __restrict__ out) {       // [NN,64] or [NN,3]
    extern __shared__ float sm[];
    float* Bs = sm;                         // [64][132]
    float* As = Bs + 64 * WS_STRIDE;        // [128][68]
    float* bs = As + 128 * AS_STRIDE;       // [64]
    float* Wl = bs + 64;                    // [192]

    const int tid    = threadIdx.x;
    const int lane   = tid & 31;
    const int warp   = tid >> 5;
    const int warp_m = warp & 3;
    const int warp_n = warp >> 2;
    const int gid    = lane >> 2;
    const int tig    = lane & 3;
    const int m0     = blockIdx.x * 128;

    for (int i = tid; i < 64 * WS_STRIDE; i += 256) Bs[i] = Wn[i];
    if (tid < 64) bs[tid] = bias[tid];
    if (FINAL && tid < 192) Wl[tid] = Wlin[tid];

    float acc[2][4][4];
    #pragma unroll
    for (int mt = 0; mt < 2; ++mt)
        #pragma unroll
        for (int nt = 0; nt < 4; ++nt)
            #pragma unroll
            for (int r = 0; r < 4; ++r) acc[mt][nt][r] = 0.f;

    #pragma unroll
    for (int ch = 0; ch < 2; ++ch) {
        const float* A = ch ? A1 : A0;
        if (ch) __syncthreads();
        #pragma unroll
        for (int r = 0; r < 8; ++r) {
            int idx = r * 256 + tid;
            int m   = idx >> 4;
            int q   = idx & 15;
            int gm  = m0 + m;
            float4 v = (gm < NN)
                ? *reinterpret_cast<const float4*>(A + (size_t)gm * DH + q * 4)
                : make_float4(0.f, 0.f, 0.f, 0.f);
            v.x = to_tf32(v.x);  v.y = to_tf32(v.y);
            v.z = to_tf32(v.z);  v.w = to_tf32(v.w);
            *reinterpret_cast<float4*>(As + m * AS_STRIDE + q * 4) = v;
        }
        __syncthreads();

        #pragma unroll
        for (int s = 0; s < 8; ++s) {
            unsigned a[2][4], b[4][2];
            int ac = s * 8 + tig;
            #pragma unroll
            for (int mt = 0; mt < 2; ++mt) {
                int r0 = warp_m * 32 + mt * 16 + gid;
                a[mt][0] = __float_as_uint(As[r0 * AS_STRIDE + ac]);
                a[mt][1] = __float_as_uint(As[(r0 + 8) * AS_STRIDE + ac]);
                a[mt][2] = __float_as_uint(As[r0 * AS_STRIDE + ac + 4]);
                a[mt][3] = __float_as_uint(As[(r0 + 8) * AS_STRIDE + ac + 4]);
            }
            int bk = ch * 64 + s * 8 + tig;
            #pragma unroll
            for (int nt = 0; nt < 4; ++nt) {
                int n = warp_n * 32 + nt * 8 + gid;
                b[nt][0] = __float_as_uint(Bs[n * WS_STRIDE + bk]);
                b[nt][1] = __float_as_uint(Bs[n * WS_STRIDE + bk + 4]);
            }
            #pragma unroll
            for (int mt = 0; mt < 2; ++mt)
                #pragma unroll
                for (int nt = 0; nt < 4; ++nt)
                    mma_tf32(acc[mt][nt], a[mt], b[nt]);
        }
    }

    if (!FINAL) {
        #pragma unroll
        for (int mt = 0; mt < 2; ++mt) {
            #pragma unroll
            for (int nt = 0; nt < 4; ++nt) {
                int col = warp_n * 32 + nt * 8 + 2 * tig;
                float b0 = bs[col], b1 = bs[col + 1];
                int r1 = m0 + warp_m * 32 + mt * 16 + gid;
                if (r1 < NN) {
                    float2 o = make_float2(fmaxf(acc[mt][nt][0] + b0, 0.f),
                                           fmaxf(acc[mt][nt][1] + b1, 0.f));
                    *reinterpret_cast<float2*>(out + (size_t)r1 * DH + col) = o;
                }
                int r2 = r1 + 8;
                if (r2 < NN) {
                    float2 o = make_float2(fmaxf(acc[mt][nt][2] + b0, 0.f),
                                           fmaxf(acc[mt][nt][3] + b1, 0.f));
                    *reinterpret_cast<float2*>(out + (size_t)r2 * DH + col) = o;
                }
            }
        }
    } else {
        __syncthreads();
        #pragma unroll
        for (int mt = 0; mt < 2; ++mt) {
            #pragma unroll
            for (int nt = 0; nt < 4; ++nt) {
                int col = warp_n * 32 + nt * 8 + 2 * tig;
                float b0 = bs[col], b1 = bs[col + 1];
                int lr1 = warp_m * 32 + mt * 16 + gid;
                *reinterpret_cast<float2*>(As + lr1 * AS_STRIDE + col) =
                    make_float2(fmaxf(acc[mt][nt][0] + b0, 0.f),
                                fmaxf(acc[mt][nt][1] + b1, 0.f));
                *reinterpret_cast<float2*>(As + (lr1 + 8) * AS_STRIDE + col) =
                    make_float2(fmaxf(acc[mt][nt][2] + b0, 0.f),
                                fmaxf(acc[mt][nt][3] + b1, 0.f));
            }
        }
        __syncthreads();
        #pragma unroll
        for (int r = 0; r < 2; ++r) {
            int idx = tid + 256 * r;
            if (idx < 384) {
                int m = idx / 3;
                int o = idx - 3 * m;
                int gm = m0 + m;
                if (gm < NN) {
                    float s = blin[o];
                    const float* hrow = As + m * AS_STRIDE;
                    const float* wrow = Wl + o * 64;
                    #pragma unroll 16
                    for (int k = 0; k < 64; ++k) s += hrow[k] * wrow[k];
                    out[(size_t)gm * 3 + o] = s;
                }
            }
        }
    }
}

// ---------------- launch ----------------
extern "C" void kernel_launch(void* const* d_in, const int* in_sizes, int n_in,
                              void* d_out, int out_size) {
    const float* x      = (const float*)d_in[0];
    const void*  ei     = d_in[1];
    const float* W1_rel = (const float*)d_in[2];
    const float* b1     = (const float*)d_in[3];
    const float* W1_rt  = (const float*)d_in[4];
    const float* W2_rel = (const float*)d_in[5];
    const float* b2     = (const float*)d_in[6];
    const float* W2_rt  = (const float*)d_in[7];
    const float* W_lin  = (const float*)d_in[8];
    const float* b_lin  = (const float*)d_in[9];
    float*       out    = (float*)d_out;

    float *agg, *h1, *Wn1, *Wn2;
    int *esrc, *cnt, *offs, *cursor;
    cudaGetSymbolAddress((void**)&agg,    g_agg);
    cudaGetSymbolAddress((void**)&h1,     g_h1);
    cudaGetSymbolAddress((void**)&Wn1,    g_Wn1);
    cudaGetSymbolAddress((void**)&Wn2,    g_Wn2);
    cudaGetSymbolAddress((void**)&esrc,   g_esrc);
    cudaGetSymbolAddress((void**)&cnt,    g_cnt);
    cudaGetSymbolAddress((void**)&offs,   g_offs);
    cudaGetSymbolAddress((void**)&cursor, g_cursor);

    const int smem = (64 * WS_STRIDE + 128 * AS_STRIDE + 64 + 192) * sizeof(float); // 69632 B
    cudaFuncSetAttribute(gemm_tc<false>, cudaFuncAttributeMaxDynamicSharedMemorySize, smem);
    cudaFuncSetAttribute(gemm_tc<true>,  cudaFuncAttributeMaxDynamicSharedMemorySize, smem);

    const int e4grid = (NE / 4 + 255) / 256;
    const int ngrid  = (NN + 255) / 256;
    const int ggrid  = (NN + 127) / 128;
    const int agrid  = (NN + 7) / 8;
    const int wgrid  = (2 * 64 * WS_STRIDE + 255) / 256;

    zero_detect<<<ngrid, 256>>>(ei, cnt);
    hist_dst<<<e4grid, 256>>>(ei, cnt);
    scan_all<<<1, 1024>>>(cnt, offs, cursor);
    place_edges<<<e4grid, 256>>>(ei, cursor, esrc);
    prep_w2<<<wgrid, 256>>>(W1_rel, W1_rt, W2_rel, W2_rt, Wn1, Wn2);

    gather_agg<<<agrid, 256>>>(x, offs, esrc, agg);
    gemm_tc<false><<<ggrid, 256, smem>>>(agg, x, Wn1, b1, nullptr, nullptr, h1);
    gather_agg<<<agrid, 256>>>(h1, offs, esrc, agg);
    gemm_tc<true ><<<ggrid, 256, smem>>>(agg, h1, Wn2, b2, W_lin, b_lin, out);
}

// round 10
// speedup vs baseline: 1.8406x; 1.8406x over previous
#include <cuda_runtime.h>
#include <cstdint>

#define NN 100000
#define NE 1600000
#define DH 64
#define SCAN_BLK 1024
#define NB ((NN + SCAN_BLK - 1) / SCAN_BLK) // 98
#define AS_STRIDE 68
#define WS_STRIDE 132

// ---------------- scratch (no allocations allowed) ----------------
__device__ float g_agg[(size_t)NN * DH];
__device__ float g_h1 [(size_t)NN * DH];
__device__ float g_Wn1[64 * WS_STRIDE];   // [n][k] tf32-rounded, k = rel(0:64)|root(64:128)
__device__ float g_Wn2[64 * WS_STRIDE];
__device__ int   g_esrc[NE];
__device__ int   g_cnt[NN];
__device__ int   g_offs[NN + 1];
__device__ int   g_cursor[NN];
__device__ int   g_bsum[NB];
__device__ int   g_is64;

__device__ __forceinline__ float to_tf32(float x) {
    unsigned u;
    asm("cvt.rna.tf32.f32 %0, %1;" : "=r"(u) : "f"(x));
    return __uint_as_float(u);
}

__device__ __forceinline__ void mma_tf32(float c[4], const unsigned a[4], const unsigned b[2]) {
    asm("mma.sync.aligned.m16n8k8.row.col.f32.tf32.tf32.f32 "
        "{%0,%1,%2,%3}, {%4,%5,%6,%7}, {%8,%9}, {%0,%1,%2,%3};"
        : "+f"(c[0]), "+f"(c[1]), "+f"(c[2]), "+f"(c[3])
        : "r"(a[0]), "r"(a[1]), "r"(a[2]), "r"(a[3]), "r"(b[0]), "r"(b[1]));
}

// ---------------- zero cnt + detect edge_index dtype ----------------
__global__ void zero_detect(const void* __restrict__ ei, int* __restrict__ cnt) {
    int i = blockIdx.x * blockDim.x + threadIdx.x;
    if (i < NN) cnt[i] = 0;
    if (i == 0) {
        const long long* p = (const long long*)ei;
        bool all64 = true;
        #pragma unroll
        for (int j = 0; j < 8; ++j) {
            long long v = p[j];
            if (v < 0 || v >= NN) all64 = false;
        }
        g_is64 = all64 ? 1 : 0;
    }
}

// ---------------- histogram over dst (4 edges/thread) ----------------
__global__ void hist_dst(const void* __restrict__ ei, int* __restrict__ cnt) {
    int i = (blockIdx.x * blockDim.x + threadIdx.x) * 4;
    if (i >= NE) return;
    int d0, d1, d2, d3;
    if (g_is64) {
        longlong4 q = *reinterpret_cast<const longlong4*>((const long long*)ei + NE + i);
        d0 = (int)q.x; d1 = (int)q.y; d2 = (int)q.z; d3 = (int)q.w;
    } else {
        int4 q = *reinterpret_cast<const int4*>((const int*)ei + NE + i);
        d0 = q.x; d1 = q.y; d2 = q.z; d3 = q.w;
    }
    atomicAdd(&cnt[d0], 1);
    atomicAdd(&cnt[d1], 1);
    atomicAdd(&cnt[d2], 1);
    atomicAdd(&cnt[d3], 1);
}

// ---------------- multi-block scan (coalesced; R6 scheme) ----------------
// per-block exclusive scan: 256 threads x 4 counts = 1024/block
__global__ void scan_blocks(const int* __restrict__ cnt,
                            int* __restrict__ offs, int* __restrict__ bsum) {
    __shared__ int sh[256];
    int t = threadIdx.x;
    int base = blockIdx.x * SCAN_BLK + t * 4;
    int c0 = (base + 0 < NN) ? cnt[base + 0] : 0;
    int c1 = (base + 1 < NN) ? cnt[base + 1] : 0;
    int c2 = (base + 2 < NN) ? cnt[base + 2] : 0;
    int c3 = (base + 3 < NN) ? cnt[base + 3] : 0;
    int s = c0 + c1 + c2 + c3;
    sh[t] = s;
    __syncthreads();
    #pragma unroll
    for (int off = 1; off < 256; off <<= 1) {
        int v = (t >= off) ? sh[t - off] : 0;
        __syncthreads();
        sh[t] += v;
        __syncthreads();
    }
    int excl = sh[t] - s;
    if (t == 255) bsum[blockIdx.x] = sh[255];
    if (base + 0 < NN) offs[base + 0] = excl;  excl += c0;
    if (base + 1 < NN) offs[base + 1] = excl;  excl += c1;
    if (base + 2 < NN) offs[base + 2] = excl;  excl += c2;
    if (base + 3 < NN) offs[base + 3] = excl;
}

__global__ void scan_bsums(int* __restrict__ bsum) {
    __shared__ int sh[128];
    int t = threadIdx.x;
    int v = (t < NB) ? bsum[t] : 0;
    sh[t] = v;
    __syncthreads();
    #pragma unroll
    for (int off = 1; off < 128; off <<= 1) {
        int u = (t >= off) ? sh[t - off] : 0;
        __syncthreads();
        sh[t] += u;
        __syncthreads();
    }
    if (t < NB) bsum[t] = sh[t] - v;
}

__global__ void add_base(int* __restrict__ offs, const int* __restrict__ bsum,
                         int* __restrict__ cursor) {
    int i = blockIdx.x * blockDim.x + threadIdx.x;
    if (i < NN) {
        int v = offs[i] + bsum[i / SCAN_BLK];
        offs[i] = v;
        cursor[i] = v;
    }
    if (i == 0) offs[NN] = NE;
}

// ---------------- place edges (CSR fill) ----------------
__global__ void place_edges(const void* __restrict__ ei,
                            int* __restrict__ cursor, int* __restrict__ esrc) {
    int i = (blockIdx.x * blockDim.x + threadIdx.x) * 4;
    if (i >= NE) return;
    int s0, s1, s2, s3, d0, d1, d2, d3;
    if (g_is64) {
        const long long* p = (const long long*)ei;
        longlong4 qs = *reinterpret_cast<const longlong4*>(p + i);
        longlong4 qd = *reinterpret_cast<const longlong4*>(p + NE + i);
        s0 = (int)qs.x; s1 = (int)qs.y; s2 = (int)qs.z; s3 = (int)qs.w;
        d0 = (int)qd.x; d1 = (int)qd.y; d2 = (int)qd.z; d3 = (int)qd.w;
    } else {
        const int* p = (const int*)ei;
        int4 qs = *reinterpret_cast<const int4*>(p + i);
        int4 qd = *reinterpret_cast<const int4*>(p + NE + i);
        s0 = qs.x; s1 = qs.y; s2 = qs.z; s3 = qs.w;
        d0 = qd.x; d1 = qd.y; d2 = qd.z; d3 = qd.w;
    }
    esrc[atomicAdd(&cursor[d0], 1)] = s0;
    esrc[atomicAdd(&cursor[d1], 1)] = s1;
    esrc[atomicAdd(&cursor[d2], 1)] = s2;
    esrc[atomicAdd(&cursor[d3], 1)] = s3;
}

// ---------------- both weight tensors -> tf32 [n][k] ----------------
__global__ void prep_w2(const float* __restrict__ W1rel, const float* __restrict__ W1rt,
                        const float* __restrict__ W2rel, const float* __restrict__ W2rt,
                        float* __restrict__ Wn1, float* __restrict__ Wn2) {
    int i = blockIdx.x * blockDim.x + threadIdx.x;
    int layer = (i >= 64 * WS_STRIDE);
    int j = i - layer * 64 * WS_STRIDE;
    if (j < 64 * WS_STRIDE && i < 2 * 64 * WS_STRIDE) {
        int n = j / WS_STRIDE;
        int k = j - n * WS_STRIDE;
        const float* Wrel = layer ? W2rel : W1rel;
        const float* Wrt  = layer ? W2rt  : W1rt;
        float v = 0.f;
        if (k < 64)       v = Wrel[n * 64 + k];
        else if (k < 128) v = Wrt [n * 64 + (k - 64)];
        (layer ? Wn2 : Wn1)[j] = to_tf32(v);
    }
}

// ---------------- gather: 1 warp/node, float2/lane, 8-edge unroll ----------------
__global__ void __launch_bounds__(256)
gather_agg(const float* __restrict__ feat,
           const int* __restrict__ offs,
           const int* __restrict__ esrc,
           float* __restrict__ agg) {
    int node = blockIdx.x * (blockDim.x >> 5) + (threadIdx.x >> 5);
    if (node >= NN) return;
    int lane = threadIdx.x & 31;
    int s0 = offs[node];
    int s1 = offs[node + 1];
    const float2* f2 = reinterpret_cast<const float2*>(feat);
    float sx = 0.f, sy = 0.f;
    int j = s0;
    for (; j + 8 <= s1; j += 8) {           // 8 independent LDG.64 in flight
        int e0 = esrc[j],     e1 = esrc[j + 1], e2 = esrc[j + 2], e3 = esrc[j + 3];
        int e4 = esrc[j + 4], e5 = esrc[j + 5], e6 = esrc[j + 6], e7 = esrc[j + 7];
        float2 v0 = f2[(size_t)e0 * 32 + lane];
        float2 v1 = f2[(size_t)e1 * 32 + lane];
        float2 v2 = f2[(size_t)e2 * 32 + lane];
        float2 v3 = f2[(size_t)e3 * 32 + lane];
        float2 v4 = f2[(size_t)e4 * 32 + lane];
        float2 v5 = f2[(size_t)e5 * 32 + lane];
        float2 v6 = f2[(size_t)e6 * 32 + lane];
        float2 v7 = f2[(size_t)e7 * 32 + lane];
        sx += (v0.x + v1.x) + (v2.x + v3.x) + (v4.x + v5.x) + (v6.x + v7.x);
        sy += (v0.y + v1.y) + (v2.y + v3.y) + (v4.y + v5.y) + (v6.y + v7.y);
    }
    for (; j + 4 <= s1; j += 4) {
        int e0 = esrc[j], e1 = esrc[j + 1], e2 = esrc[j + 2], e3 = esrc[j + 3];
        float2 v0 = f2[(size_t)e0 * 32 + lane];
        float2 v1 = f2[(size_t)e1 * 32 + lane];
        float2 v2 = f2[(size_t)e2 * 32 + lane];
        float2 v3 = f2[(size_t)e3 * 32 + lane];
        sx += (v0.x + v1.x) + (v2.x + v3.x);
        sy += (v0.y + v1.y) + (v2.y + v3.y);
    }
    for (; j < s1; ++j) {
        float2 v = f2[(size_t)esrc[j] * 32 + lane];
        sx += v.x; sy += v.y;
    }
    reinterpret_cast<float2*>(agg)[(size_t)node * 32 + lane] = make_float2(sx, sy);
}

// ---------------- tf32 tensor-core dual-GEMM (+ fused head on FINAL) ----------
template<bool FINAL>
__global__ void __launch_bounds__(256)
gemm_tc(const float* __restrict__ A0,    // agg [NN,64]
        const float* __restrict__ A1,    // xin [NN,64]
        const float* __restrict__ Wn,    // [64][WS_STRIDE] tf32
        const float* __restrict__ bias,  // [64]
        const float* __restrict__ Wlin,  // [3,64]  (FINAL)
        const float* __restrict__ blin,  // [3]     (FINAL)
        float* __restrict__ out) {       // [NN,64] or [NN,3]
    extern __shared__ float sm[];
    float* Bs = sm;                         // [64][132]
    float* As = Bs + 64 * WS_STRIDE;        // [128][68]
    float* bs = As + 128 * AS_STRIDE;       // [64]
    float* Wl = bs + 64;                    // [192]

    const int tid    = threadIdx.x;
    const int lane   = tid & 31;
    const int warp   = tid >> 5;
    const int warp_m = warp & 3;
    const int warp_n = warp >> 2;
    const int gid    = lane >> 2;
    const int tig    = lane & 3;
    const int m0     = blockIdx.x * 128;

    for (int i = tid; i < 64 * WS_STRIDE; i += 256) Bs[i] = Wn[i];
    if (tid < 64) bs[tid] = bias[tid];
    if (FINAL && tid < 192) Wl[tid] = Wlin[tid];

    float acc[2][4][4];
    #pragma unroll
    for (int mt = 0; mt < 2; ++mt)
        #pragma unroll
        for (int nt = 0; nt < 4; ++nt)
            #pragma unroll
            for (int r = 0; r < 4; ++r) acc[mt][nt][r] = 0.f;

    #pragma unroll
    for (int ch = 0; ch < 2; ++ch) {
        const float* A = ch ? A1 : A0;
        if (ch) __syncthreads();
        #pragma unroll
        for (int r = 0; r < 8; ++r) {
            int idx = r * 256 + tid;
            int m   = idx >> 4;
            int q   = idx & 15;
            int gm  = m0 + m;
            float4 v = (gm < NN)
                ? *reinterpret_cast<const float4*>(A + (size_t)gm * DH + q * 4)
                : make_float4(0.f, 0.f, 0.f, 0.f);
            v.x = to_tf32(v.x);  v.y = to_tf32(v.y);
            v.z = to_tf32(v.z);  v.w = to_tf32(v.w);
            *reinterpret_cast<float4*>(As + m * AS_STRIDE + q * 4) = v;
        }
        __syncthreads();

        #pragma unroll
        for (int s = 0; s < 8; ++s) {
            unsigned a[2][4], b[4][2];
            int ac = s * 8 + tig;
            #pragma unroll
            for (int mt = 0; mt < 2; ++mt) {
                int r0 = warp_m * 32 + mt * 16 + gid;
                a[mt][0] = __float_as_uint(As[r0 * AS_STRIDE + ac]);
                a[mt][1] = __float_as_uint(As[(r0 + 8) * AS_STRIDE + ac]);
                a[mt][2] = __float_as_uint(As[r0 * AS_STRIDE + ac + 4]);
                a[mt][3] = __float_as_uint(As[(r0 + 8) * AS_STRIDE + ac + 4]);
            }
            int bk = ch * 64 + s * 8 + tig;
            #pragma unroll
            for (int nt = 0; nt < 4; ++nt) {
                int n = warp_n * 32 + nt * 8 + gid;
                b[nt][0] = __float_as_uint(Bs[n * WS_STRIDE + bk]);
                b[nt][1] = __float_as_uint(Bs[n * WS_STRIDE + bk + 4]);
            }
            #pragma unroll
            for (int mt = 0; mt < 2; ++mt)
                #pragma unroll
                for (int nt = 0; nt < 4; ++nt)
                    mma_tf32(acc[mt][nt], a[mt], b[nt]);
        }
    }

    if (!FINAL) {
        #pragma unroll
        for (int mt = 0; mt < 2; ++mt) {
            #pragma unroll
            for (int nt = 0; nt < 4; ++nt) {
                int col = warp_n * 32 + nt * 8 + 2 * tig;
                float b0 = bs[col], b1 = bs[col + 1];
                int r1 = m0 + warp_m * 32 + mt * 16 + gid;
                if (r1 < NN) {
                    float2 o = make_float2(fmaxf(acc[mt][nt][0] + b0, 0.f),
                                           fmaxf(acc[mt][nt][1] + b1, 0.f));
                    *reinterpret_cast<float2*>(out + (size_t)r1 * DH + col) = o;
                }
                int r2 = r1 + 8;
                if (r2 < NN) {
                    float2 o = make_float2(fmaxf(acc[mt][nt][2] + b0, 0.f),
                                           fmaxf(acc[mt][nt][3] + b1, 0.f));
                    *reinterpret_cast<float2*>(out + (size_t)r2 * DH + col) = o;
                }
            }
        }
    } else {
        __syncthreads();
        #pragma unroll
        for (int mt = 0; mt < 2; ++mt) {
            #pragma unroll
            for (int nt = 0; nt < 4; ++nt) {
                int col = warp_n * 32 + nt * 8 + 2 * tig;
                float b0 = bs[col], b1 = bs[col + 1];
                int lr1 = warp_m * 32 + mt * 16 + gid;
                *reinterpret_cast<float2*>(As + lr1 * AS_STRIDE + col) =
                    make_float2(fmaxf(acc[mt][nt][0] + b0, 0.f),
                                fmaxf(acc[mt][nt][1] + b1, 0.f));
                *reinterpret_cast<float2*>(As + (lr1 + 8) * AS_STRIDE + col) =
                    make_float2(fmaxf(acc[mt][nt][2] + b0, 0.f),
                                fmaxf(acc[mt][nt][3] + b1, 0.f));
            }
        }
        __syncthreads();
        #pragma unroll
        for (int r = 0; r < 2; ++r) {
            int idx = tid + 256 * r;
            if (idx < 384) {
                int m = idx / 3;
                int o = idx - 3 * m;
                int gm = m0 + m;
                if (gm < NN) {
                    float s = blin[o];
                    const float* hrow = As + m * AS_STRIDE;
                    const float* wrow = Wl + o * 64;
                    #pragma unroll 16
                    for (int k = 0; k < 64; ++k) s += hrow[k] * wrow[k];
                    out[(size_t)gm * 3 + o] = s;
                }
            }
        }
    }
}

// ---------------- launch ----------------
extern "C" void kernel_launch(void* const* d_in, const int* in_sizes, int n_in,
                              void* d_out, int out_size) {
    const float* x      = (const float*)d_in[0];
    const void*  ei     = d_in[1];
    const float* W1_rel = (const float*)d_in[2];
    const float* b1     = (const float*)d_in[3];
    const float* W1_rt  = (const float*)d_in[4];
    const float* W2_rel = (const float*)d_in[5];
    const float* b2     = (const float*)d_in[6];
    const float* W2_rt  = (const float*)d_in[7];
    const float* W_lin  = (const float*)d_in[8];
    const float* b_lin  = (const float*)d_in[9];
    float*       out    = (float*)d_out;

    float *agg, *h1, *Wn1, *Wn2;
    int *esrc, *cnt, *offs, *cursor, *bsum;
    cudaGetSymbolAddress((void**)&agg,    g_agg);
    cudaGetSymbolAddress((void**)&h1,     g_h1);
    cudaGetSymbolAddress((void**)&Wn1,    g_Wn1);
    cudaGetSymbolAddress((void**)&Wn2,    g_Wn2);
    cudaGetSymbolAddress((void**)&esrc,   g_esrc);
    cudaGetSymbolAddress((void**)&cnt,    g_cnt);
    cudaGetSymbolAddress((void**)&offs,   g_offs);
    cudaGetSymbolAddress((void**)&cursor, g_cursor);
    cudaGetSymbolAddress((void**)&bsum,   g_bsum);

    const int smem = (64 * WS_STRIDE + 128 * AS_STRIDE + 64 + 192) * sizeof(float); // 69632 B
    cudaFuncSetAttribute(gemm_tc<false>, cudaFuncAttributeMaxDynamicSharedMemorySize, smem);
    cudaFuncSetAttribute(gemm_tc<true>,  cudaFuncAttributeMaxDynamicSharedMemorySize, smem);

    const int e4grid = (NE / 4 + 255) / 256;
    const int ngrid  = (NN + 255) / 256;
    const int ggrid  = (NN + 127) / 128;
    const int agrid  = (NN + 7) / 8;
    const int wgrid  = (2 * 64 * WS_STRIDE + 255) / 256;

    zero_detect<<<ngrid, 256>>>(ei, cnt);
    hist_dst<<<e4grid, 256>>>(ei, cnt);
    scan_blocks<<<NB, 256>>>(cnt, offs, bsum);
    scan_bsums<<<1, 128>>>(bsum);
    add_base<<<ngrid, 256>>>(offs, bsum, cursor);
    place_edges<<<e4grid, 256>>>(ei, cursor, esrc);
    prep_w2<<<wgrid, 256>>>(W1_rel, W1_rt, W2_rel, W2_rt, Wn1, Wn2);

    gather_agg<<<agrid, 256>>>(x, offs, esrc, agg);
    gemm_tc<false><<<ggrid, 256, smem>>>(agg, x, Wn1, b1, nullptr, nullptr, h1);
    gather_agg<<<agrid, 256>>>(h1, offs, esrc, agg);
    gemm_tc<true ><<<ggrid, 256, smem>>>(agg, h1, Wn2, b2, W_lin, b_lin, out);
}

// round 11
// speedup vs baseline: 1.8619x; 1.0116x over previous
#include <cuda_runtime.h>
#include <cstdint>

#define NN 100000
#define NE 1600000
#define DH 64
#define SCAN_BLK 1024
#define NB ((NN + SCAN_BLK - 1) / SCAN_BLK) // 98
#define AS_STRIDE 68
#define WS_STRIDE 132

// ---------------- scratch (no allocations allowed) ----------------
__device__ float g_agg[(size_t)NN * DH];
__device__ float g_h1 [(size_t)NN * DH];
__device__ float g_Wn1[64 * WS_STRIDE];   // [n][k] tf32-rounded, k = rel(0:64)|root(64:128)
__device__ float g_Wn2[64 * WS_STRIDE];
__device__ int   g_esrc[NE];
__device__ int   g_cnt[NN];
__device__ int   g_offs[NN + 1];
__device__ int   g_cursor[NN];
__device__ int   g_bsum[NB];
__device__ int   g_is64;

__device__ __forceinline__ float to_tf32(float x) {
    unsigned u;
    asm("cvt.rna.tf32.f32 %0, %1;" : "=r"(u) : "f"(x));
    return __uint_as_float(u);
}

__device__ __forceinline__ void mma_tf32(float c[4], const unsigned a[4], const unsigned b[2]) {
    asm("mma.sync.aligned.m16n8k8.row.col.f32.tf32.tf32.f32 "
        "{%0,%1,%2,%3}, {%4,%5,%6,%7}, {%8,%9}, {%0,%1,%2,%3};"
        : "+f"(c[0]), "+f"(c[1]), "+f"(c[2]), "+f"(c[3])
        : "r"(a[0]), "r"(a[1]), "r"(a[2]), "r"(a[3]), "r"(b[0]), "r"(b[1]));
}

// ---------------- zero cnt + detect edge_index dtype ----------------
__global__ void zero_detect(const void* __restrict__ ei, int* __restrict__ cnt) {
    int i = blockIdx.x * blockDim.x + threadIdx.x;
    if (i < NN) cnt[i] = 0;
    if (i == 0) {
        const long long* p = (const long long*)ei;
        bool all64 = true;
        #pragma unroll
        for (int j = 0; j < 8; ++j) {
            long long v = p[j];
            if (v < 0 || v >= NN) all64 = false;
        }
        g_is64 = all64 ? 1 : 0;
    }
}

// ---------------- histogram over dst (4 edges/thread) ----------------
__global__ void hist_dst(const void* __restrict__ ei, int* __restrict__ cnt) {
    int i = (blockIdx.x * blockDim.x + threadIdx.x) * 4;
    if (i >= NE) return;
    int d0, d1, d2, d3;
    if (g_is64) {
        longlong4 q = *reinterpret_cast<const longlong4*>((const long long*)ei + NE + i);
        d0 = (int)q.x; d1 = (int)q.y; d2 = (int)q.z; d3 = (int)q.w;
    } else {
        int4 q = *reinterpret_cast<const int4*>((const int*)ei + NE + i);
        d0 = q.x; d1 = q.y; d2 = q.z; d3 = q.w;
    }
    atomicAdd(&cnt[d0], 1);
    atomicAdd(&cnt[d1], 1);
    atomicAdd(&cnt[d2], 1);
    atomicAdd(&cnt[d3], 1);
}

// ---------------- multi-block scan (coalesced) ----------------
__global__ void scan_blocks(const int* __restrict__ cnt,
                            int* __restrict__ offs, int* __restrict__ bsum) {
    __shared__ int sh[256];
    int t = threadIdx.x;
    int base = blockIdx.x * SCAN_BLK + t * 4;
    int c0 = (base + 0 < NN) ? cnt[base + 0] : 0;
    int c1 = (base + 1 < NN) ? cnt[base + 1] : 0;
    int c2 = (base + 2 < NN) ? cnt[base + 2] : 0;
    int c3 = (base + 3 < NN) ? cnt[base + 3] : 0;
    int s = c0 + c1 + c2 + c3;
    sh[t] = s;
    __syncthreads();
    #pragma unroll
    for (int off = 1; off < 256; off <<= 1) {
        int v = (t >= off) ? sh[t - off] : 0;
        __syncthreads();
        sh[t] += v;
        __syncthreads();
    }
    int excl = sh[t] - s;
    if (t == 255) bsum[blockIdx.x] = sh[255];
    if (base + 0 < NN) offs[base + 0] = excl;  excl += c0;
    if (base + 1 < NN) offs[base + 1] = excl;  excl += c1;
    if (base + 2 < NN) offs[base + 2] = excl;  excl += c2;
    if (base + 3 < NN) offs[base + 3] = excl;
}

__global__ void scan_bsums(int* __restrict__ bsum) {
    __shared__ int sh[128];
    int t = threadIdx.x;
    int v = (t < NB) ? bsum[t] : 0;
    sh[t] = v;
    __syncthreads();
    #pragma unroll
    for (int off = 1; off < 128; off <<= 1) {
        int u = (t >= off) ? sh[t - off] : 0;
        __syncthreads();
        sh[t] += u;
        __syncthreads();
    }
    if (t < NB) bsum[t] = sh[t] - v;
}

__global__ void add_base(int* __restrict__ offs, const int* __restrict__ bsum,
                         int* __restrict__ cursor) {
    int i = blockIdx.x * blockDim.x + threadIdx.x;
    if (i < NN) {
        int v = offs[i] + bsum[i / SCAN_BLK];
        offs[i] = v;
        cursor[i] = v;
    }
    if (i == 0) offs[NN] = NE;
}

// ---------------- place edges (CSR fill) ----------------
__global__ void place_edges(const void* __restrict__ ei,
                            int* __restrict__ cursor, int* __restrict__ esrc) {
    int i = (blockIdx.x * blockDim.x + threadIdx.x) * 4;
    if (i >= NE) return;
    int s0, s1, s2, s3, d0, d1, d2, d3;
    if (g_is64) {
        const long long* p = (const long long*)ei;
        longlong4 qs = *reinterpret_cast<const longlong4*>(p + i);
        longlong4 qd = *reinterpret_cast<const longlong4*>(p + NE + i);
        s0 = (int)qs.x; s1 = (int)qs.y; s2 = (int)qs.z; s3 = (int)qs.w;
        d0 = (int)qd.x; d1 = (int)qd.y; d2 = (int)qd.z; d3 = (int)qd.w;
    } else {
        const int* p = (const int*)ei;
        int4 qs = *reinterpret_cast<const int4*>(p + i);
        int4 qd = *reinterpret_cast<const int4*>(p + NE + i);
        s0 = qs.x; s1 = qs.y; s2 = qs.z; s3 = qs.w;
        d0 = qd.x; d1 = qd.y; d2 = qd.z; d3 = qd.w;
    }
    esrc[atomicAdd(&cursor[d0], 1)] = s0;
    esrc[atomicAdd(&cursor[d1], 1)] = s1;
    esrc[atomicAdd(&cursor[d2], 1)] = s2;
    esrc[atomicAdd(&cursor[d3], 1)] = s3;
}

// ---------------- both weight tensors -> tf32 [n][k] ----------------
__global__ void prep_w2(const float* __restrict__ W1rel, const float* __restrict__ W1rt,
                        const float* __restrict__ W2rel, const float* __restrict__ W2rt,
                        float* __restrict__ Wn1, float* __restrict__ Wn2) {
    int i = blockIdx.x * blockDim.x + threadIdx.x;
    int layer = (i >= 64 * WS_STRIDE);
    int j = i - layer * 64 * WS_STRIDE;
    if (j < 64 * WS_STRIDE && i < 2 * 64 * WS_STRIDE) {
        int n = j / WS_STRIDE;
        int k = j - n * WS_STRIDE;
        const float* Wrel = layer ? W2rel : W1rel;
        const float* Wrt  = layer ? W2rt  : W1rt;
        float v = 0.f;
        if (k < 64)       v = Wrel[n * 64 + k];
        else if (k < 128) v = Wrt [n * 64 + (k - 64)];
        (layer ? Wn2 : Wn1)[j] = to_tf32(v);
    }
}

// ---------------- gather: float4/lane, 2 edges/warp-instr, 4-deep MLP ----------
__global__ void __launch_bounds__(256)
gather_agg(const float4* __restrict__ f4,     // feat as [NN*16] float4
           const int* __restrict__ offs,
           const int* __restrict__ esrc,
           float4* __restrict__ agg) {        // [NN*16]
    int node = blockIdx.x * (blockDim.x >> 5) + (threadIdx.x >> 5);
    if (node >= NN) return;
    int lane = threadIdx.x & 31;
    int half = lane >> 4;        // 0/1: which edge of the pair
    int sub  = lane & 15;        // float4 column within the 256B row
    int s0 = offs[node];
    int s1 = offs[node + 1];
    float ax = 0.f, ay = 0.f, az = 0.f, aw = 0.f;
    int j = s0;
    for (; j + 8 <= s1; j += 8) {       // 4 independent LDG.128 per lane
        int e0 = esrc[j + half];
        int e1 = esrc[j + 2 + half];
        int e2 = esrc[j + 4 + half];
        int e3 = esrc[j + 6 + half];
        float4 v0 = f4[(size_t)e0 * 16 + sub];
        float4 v1 = f4[(size_t)e1 * 16 + sub];
        float4 v2 = f4[(size_t)e2 * 16 + sub];
        float4 v3 = f4[(size_t)e3 * 16 + sub];
        ax += (v0.x + v1.x) + (v2.x + v3.x);
        ay += (v0.y + v1.y) + (v2.y + v3.y);
        az += (v0.z + v1.z) + (v2.z + v3.z);
        aw += (v0.w + v1.w) + (v2.w + v3.w);
    }
    for (; j + 4 <= s1; j += 4) {       // 2 independent loads
        int e0 = esrc[j + half];
        int e1 = esrc[j + 2 + half];
        float4 v0 = f4[(size_t)e0 * 16 + sub];
        float4 v1 = f4[(size_t)e1 * 16 + sub];
        ax += v0.x + v1.x;  ay += v0.y + v1.y;
        az += v0.z + v1.z;  aw += v0.w + v1.w;
    }
    for (; j + 2 <= s1; j += 2) {
        int e = esrc[j + half];
        float4 v = f4[(size_t)e * 16 + sub];
        ax += v.x;  ay += v.y;  az += v.z;  aw += v.w;
    }
    if (j < s1 && half == 0) {          // odd leftover: half 0 only
        float4 v = f4[(size_t)esrc[j] * 16 + sub];
        ax += v.x;  ay += v.y;  az += v.z;  aw += v.w;
    }
    // fold the two halves (lane i <-> lane i^16)
    ax += __shfl_xor_sync(0xffffffffu, ax, 16);
    ay += __shfl_xor_sync(0xffffffffu, ay, 16);
    az += __shfl_xor_sync(0xffffffffu, az, 16);
    aw += __shfl_xor_sync(0xffffffffu, aw, 16);
    if (half == 0) agg[(size_t)node * 16 + sub] = make_float4(ax, ay, az, aw);
}

// ---------------- tf32 tensor-core dual-GEMM (+ fused head on FINAL) ----------
template<bool FINAL>
__global__ void __launch_bounds__(256)
gemm_tc(const float* __restrict__ A0,    // agg [NN,64]
        const float* __restrict__ A1,    // xin [NN,64]
        const float* __restrict__ Wn,    // [64][WS_STRIDE] tf32
        const float* __restrict__ bias,  // [64]
        const float* __restrict__ Wlin,  // [3,64]  (FINAL)
        const float* __restrict__ blin,  // [3]     (FINAL)
        float* __restrict__ out) {       // [NN,64] or [NN,3]
    extern __shared__ float sm[];
    float* Bs = sm;                         // [64][132]
    float* As = Bs + 64 * WS_STRIDE;        // [128][68]
    float* bs = As + 128 * AS_STRIDE;       // [64]
    float* Wl = bs + 64;                    // [192]

    const int tid    = threadIdx.x;
    const int lane   = tid & 31;
    const int warp   = tid >> 5;
    const int warp_m = warp & 3;
    const int warp_n = warp >> 2;
    const int gid    = lane >> 2;
    const int tig    = lane & 3;
    const int m0     = blockIdx.x * 128;

    for (int i = tid; i < 64 * WS_STRIDE; i += 256) Bs[i] = Wn[i];
    if (tid < 64) bs[tid] = bias[tid];
    if (FINAL && tid < 192) Wl[tid] = Wlin[tid];

    float acc[2][4][4];
    #pragma unroll
    for (int mt = 0; mt < 2; ++mt)
        #pragma unroll
        for (int nt = 0; nt < 4; ++nt)
            #pragma unroll
            for (int r = 0; r < 4; ++r) acc[mt][nt][r] = 0.f;

    #pragma unroll
    for (int ch = 0; ch < 2; ++ch) {
        const float* A = ch ? A1 : A0;
        if (ch) __syncthreads();
        #pragma unroll
        for (int r = 0; r < 8; ++r) {
            int idx = r * 256 + tid;
            int m   = idx >> 4;
            int q   = idx & 15;
            int gm  = m0 + m;
            float4 v = (gm < NN)
                ? *reinterpret_cast<const float4*>(A + (size_t)gm * DH + q * 4)
                : make_float4(0.f, 0.f, 0.f, 0.f);
            v.x = to_tf32(v.x);  v.y = to_tf32(v.y);
            v.z = to_tf32(v.z);  v.w = to_tf32(v.w);
            *reinterpret_cast<float4*>(As + m * AS_STRIDE + q * 4) = v;
        }
        __syncthreads();

        #pragma unroll
        for (int s = 0; s < 8; ++s) {
            unsigned a[2][4], b[4][2];
            int ac = s * 8 + tig;
            #pragma unroll
            for (int mt = 0; mt < 2; ++mt) {
                int r0 = warp_m * 32 + mt * 16 + gid;
                a[mt][0] = __float_as_uint(As[r0 * AS_STRIDE + ac]);
                a[mt][1] = __float_as_uint(As[(r0 + 8) * AS_STRIDE + ac]);
                a[mt][2] = __float_as_uint(As[r0 * AS_STRIDE + ac + 4]);
                a[mt][3] = __float_as_uint(As[(r0 + 8) * AS_STRIDE + ac + 4]);
            }
            int bk = ch * 64 + s * 8 + tig;
            #pragma unroll
            for (int nt = 0; nt < 4; ++nt) {
                int n = warp_n * 32 + nt * 8 + gid;
                b[nt][0] = __float_as_uint(Bs[n * WS_STRIDE + bk]);
                b[nt][1] = __float_as_uint(Bs[n * WS_STRIDE + bk + 4]);
            }
            #pragma unroll
            for (int mt = 0; mt < 2; ++mt)
                #pragma unroll
                for (int nt = 0; nt < 4; ++nt)
                    mma_tf32(acc[mt][nt], a[mt], b[nt]);
        }
    }

    if (!FINAL) {
        #pragma unroll
        for (int mt = 0; mt < 2; ++mt) {
            #pragma unroll
            for (int nt = 0; nt < 4; ++nt) {
                int col = warp_n * 32 + nt * 8 + 2 * tig;
                float b0 = bs[col], b1 = bs[col + 1];
                int r1 = m0 + warp_m * 32 + mt * 16 + gid;
                if (r1 < NN) {
                    float2 o = make_float2(fmaxf(acc[mt][nt][0] + b0, 0.f),
                                           fmaxf(acc[mt][nt][1] + b1, 0.f));
                    *reinterpret_cast<float2*>(out + (size_t)r1 * DH + col) = o;
                }
                int r2 = r1 + 8;
                if (r2 < NN) {
                    float2 o = make_float2(fmaxf(acc[mt][nt][2] + b0, 0.f),
                                           fmaxf(acc[mt][nt][3] + b1, 0.f));
                    *reinterpret_cast<float2*>(out + (size_t)r2 * DH + col) = o;
                }
            }
        }
    } else {
        __syncthreads();
        #pragma unroll
        for (int mt = 0; mt < 2; ++mt) {
            #pragma unroll
            for (int nt = 0; nt < 4; ++nt) {
                int col = warp_n * 32 + nt * 8 + 2 * tig;
                float b0 = bs[col], b1 = bs[col + 1];
                int lr1 = warp_m * 32 + mt * 16 + gid;
                *reinterpret_cast<float2*>(As + lr1 * AS_STRIDE + col) =
                    make_float2(fmaxf(acc[mt][nt][0] + b0, 0.f),
                                fmaxf(acc[mt][nt][1] + b1, 0.f));
                *reinterpret_cast<float2*>(As + (lr1 + 8) * AS_STRIDE + col) =
                    make_float2(fmaxf(acc[mt][nt][2] + b0, 0.f),
                                fmaxf(acc[mt][nt][3] + b1, 0.f));
            }
        }
        __syncthreads();
        #pragma unroll
        for (int r = 0; r < 2; ++r) {
            int idx = tid + 256 * r;
            if (idx < 384) {
                int m = idx / 3;
                int o = idx - 3 * m;
                int gm = m0 + m;
                if (gm < NN) {
                    float s = blin[o];
                    const float* hrow = As + m * AS_STRIDE;
                    const float* wrow = Wl + o * 64;
                    #pragma unroll 16
                    for (int k = 0; k < 64; ++k) s += hrow[k] * wrow[k];
                    out[(size_t)gm * 3 + o] = s;
                }
            }
        }
    }
}

// ---------------- launch ----------------
extern "C" void kernel_launch(void* const* d_in, const int* in_sizes, int n_in,
                              void* d_out, int out_size) {
    const float* x      = (const float*)d_in[0];
    const void*  ei     = d_in[1];
    const float* W1_rel = (const float*)d_in[2];
    const float* b1     = (const float*)d_in[3];
    const float* W1_rt  = (const float*)d_in[4];
    const float* W2_rel = (const float*)d_in[5];
    const float* b2     = (const float*)d_in[6];
    const float* W2_rt  = (const float*)d_in[7];
    const float* W_lin  = (const float*)d_in[8];
    const float* b_lin  = (const float*)d_in[9];
    float*       out    = (float*)d_out;

    float *agg, *h1, *Wn1, *Wn2;
    int *esrc, *cnt, *offs, *cursor, *bsum;
    cudaGetSymbolAddress((void**)&agg,    g_agg);
    cudaGetSymbolAddress((void**)&h1,     g_h1);
    cudaGetSymbolAddress((void**)&Wn1,    g_Wn1);
    cudaGetSymbolAddress((void**)&Wn2,    g_Wn2);
    cudaGetSymbolAddress((void**)&esrc,   g_esrc);
    cudaGetSymbolAddress((void**)&cnt,    g_cnt);
    cudaGetSymbolAddress((void**)&offs,   g_offs);
    cudaGetSymbolAddress((void**)&cursor, g_cursor);
    cudaGetSymbolAddress((void**)&bsum,   g_bsum);

    const int smem = (64 * WS_STRIDE + 128 * AS_STRIDE + 64 + 192) * sizeof(float); // 69632 B
    cudaFuncSetAttribute(gemm_tc<false>, cudaFuncAttributeMaxDynamicSharedMemorySize, smem);
    cudaFuncSetAttribute(gemm_tc<true>,  cudaFuncAttributeMaxDynamicSharedMemorySize, smem);

    const int e4grid = (NE / 4 + 255) / 256;
    const int ngrid  = (NN + 255) / 256;
    const int ggrid  = (NN + 127) / 128;
    const int agrid  = (NN + 7) / 8;
    const int wgrid  = (2 * 64 * WS_STRIDE + 255) / 256;

    zero_detect<<<ngrid, 256>>>(ei, cnt);
    hist_dst<<<e4grid, 256>>>(ei, cnt);
    scan_blocks<<<NB, 256>>>(cnt, offs, bsum);
    scan_bsums<<<1, 128>>>(bsum);
    add_base<<<ngrid, 256>>>(offs, bsum, cursor);
    place_edges<<<e4grid, 256>>>(ei, cursor, esrc);
    prep_w2<<<wgrid, 256>>>(W1_rel, W1_rt, W2_rel, W2_rt, Wn1, Wn2);

    gather_agg<<<agrid, 256>>>((const float4*)x, offs, esrc, (float4*)agg);
    gemm_tc<false><<<ggrid, 256, smem>>>(agg, x, Wn1, b1, nullptr, nullptr, h1);
    gather_agg<<<agrid, 256>>>((const float4*)h1, offs, esrc, (float4*)agg);
    gemm_tc<true ><<<ggrid, 256, smem>>>(agg, h1, Wn2, b2, W_lin, b_lin, out);
}